// round 1
// baseline (speedup 1.0000x reference)
#include <cuda_runtime.h>
#include <math.h>

#define Nn 2048
#define Fd 256
#define Hh 8
#define NH (Nn*Hh)
#define IC 32            // i-chunks for deterministic partial reduction
#define RPC (Nn/IC)      // 64 rows per chunk

// scratch (static device globals: no allocation allowed)
__device__ float g_qk[NH];
__device__ float g_v[Nn*Fd];
__device__ float g_Zp[IC*NH];
__device__ float g_rZ[NH];
__device__ float g_P[Nn*Nn];     // attn_mean, 16MB
__device__ float g_U[Nn*Fd];     // updated nodes
__device__ float g_C[Nn*Nn];     // conn (raw -> normalized), 16MB

// ---------------- projections: qk[N,H], v[N,F] ----------------
__global__ void qkv_kernel(const float* __restrict__ X, const float* __restrict__ Wq,
                           const float* __restrict__ Wk, const float* __restrict__ Wv) {
    __shared__ float xs[Fd];
    int i = blockIdx.x;
    int t = threadIdx.x;
    xs[t] = X[i*Fd + t];
    __syncthreads();
    // v[i,t] = (1/16) * sum_c x[c] * Wv[c,t]
    float acc = 0.f;
    #pragma unroll 8
    for (int c = 0; c < Fd; c++) acc = fmaf(xs[c], Wv[c*Fd + t], acc);
    g_v[i*Fd + t] = acc * 0.0625f;
    // qk[i,h] = (q+k) * (1/16) / sqrt(8); warp w handles head h=w
    int w = t >> 5, lane = t & 31;
    float qa = 0.f, ka = 0.f;
    #pragma unroll
    for (int c = lane; c < Fd; c += 32) {
        float x = xs[c];
        qa = fmaf(x, Wq[c*Hh + w], qa);
        ka = fmaf(x, Wk[c*Hh + w], ka);
    }
    #pragma unroll
    for (int o = 16; o > 0; o >>= 1) {
        qa += __shfl_down_sync(0xffffffffu, qa, o);
        ka += __shfl_down_sync(0xffffffffu, ka, o);
    }
    if (lane == 0) {
        g_qk[i*Hh + w] = (qa + ka) * (0.0625f * 0.3535533905932738f);
    }
}

// ---------------- pass B: column-wise softmax denominators ----------------
// Z[j,h] = sum_i exp(leakyrelu(qk[i,h] + e[i,j])) over unmasked i.
// Deterministic: chunked partials over i, reduced in zred_kernel.
__global__ void colz_kernel(const float* __restrict__ bond, const float* __restrict__ dist,
                            const float* __restrict__ deg, const float* __restrict__ pwb,
                            const float* __restrict__ pwbc, const float* __restrict__ pwg) {
    __shared__ float qs[RPC*Hh];
    int j = blockIdx.x*256 + threadIdx.x;
    int i0 = blockIdx.y*RPC;
    for (int t = threadIdx.x; t < RPC*Hh; t += 256) qs[t] = g_qk[i0*Hh + t];
    __syncthreads();
    float cb = pwb[0]*pwbc[0], wg = pwg[0];
    float z[Hh];
    #pragma unroll
    for (int h = 0; h < Hh; h++) z[h] = 0.f;
    for (int ii = 0; ii < RPC; ii++) {
        size_t idx = (size_t)(i0+ii)*Nn + j;
        float dg = deg[idx];
        if (dg > 0.f) {
            float e = fmaf(bond[idx], cb, dist[idx]*wg);
            #pragma unroll
            for (int h = 0; h < Hh; h++) {
                float s = qs[ii*Hh + h] + e;
                z[h] += __expf(fmaxf(s, 0.2f*s));   // leakyrelu(s,0.2)=max(s,0.2s)
            }
        }
    }
    float* zp = &g_Zp[(size_t)blockIdx.y*NH + (size_t)j*Hh];
    #pragma unroll
    for (int h = 0; h < Hh; h++) zp[h] = z[h];
}

__global__ void zred_kernel() {
    int t = blockIdx.x*blockDim.x + threadIdx.x;   // < NH
    float s = 0.f;
    #pragma unroll
    for (int c = 0; c < IC; c++) s += g_Zp[(size_t)c*NH + t];
    g_rZ[t] = 1.f / s;
}

// ---------------- pass C: P[i,j] = mean_h exp(s)/Z[j,h] ----------------
__global__ void attnp_kernel(const float* __restrict__ bond, const float* __restrict__ dist,
                             const float* __restrict__ deg, const float* __restrict__ pwb,
                             const float* __restrict__ pwbc, const float* __restrict__ pwg) {
    __shared__ float qs[RPC*Hh];
    int j = blockIdx.x*256 + threadIdx.x;
    int i0 = blockIdx.y*RPC;
    for (int t = threadIdx.x; t < RPC*Hh; t += 256) qs[t] = g_qk[i0*Hh + t];
    __syncthreads();
    float rz[Hh];
    #pragma unroll
    for (int h = 0; h < Hh; h++) rz[h] = g_rZ[(size_t)j*Hh + h];
    float cb = pwb[0]*pwbc[0], wg = pwg[0];
    for (int ii = 0; ii < RPC; ii++) {
        size_t idx = (size_t)(i0+ii)*Nn + j;
        float dg = deg[idx];
        float p = 0.f;
        if (dg > 0.f) {
            float e = fmaf(bond[idx], cb, dist[idx]*wg);
            #pragma unroll
            for (int h = 0; h < Hh; h++) {
                float s = qs[ii*Hh + h] + e;
                p = fmaf(__expf(fmaxf(s, 0.2f*s)), rz[h], p);
            }
        }
        g_P[idx] = p * 0.125f;
    }
}

// ---------------- GEMM D: agg = P[N,N] @ v[N,F]; U = elu(agg) ----------------
// BM=BN=64, BK=16, 256 threads, 4x4 per thread. Grid (F/64, N/64) = (4,32).
__global__ void gemm_pv_kernel(float* __restrict__ outU) {
    __shared__ float As[16][64];
    __shared__ float Bs[16][64];
    int tid = threadIdx.x;
    int bi = blockIdx.y * 64;
    int bc = blockIdx.x * 64;
    int arow = tid >> 2,  acol = (tid & 3)  << 2;
    int brow = tid >> 4,  bcol = (tid & 15) << 2;
    int ty   = tid >> 4,  tx   = tid & 15;
    float acc[4][4] = {};
    for (int k0 = 0; k0 < Nn; k0 += 16) {
        float4 a = *(const float4*)&g_P[(size_t)(bi + arow)*Nn + k0 + acol];
        float4 b = *(const float4*)&g_v[(size_t)(k0 + brow)*Fd + bc + bcol];
        As[acol+0][arow] = a.x; As[acol+1][arow] = a.y;
        As[acol+2][arow] = a.z; As[acol+3][arow] = a.w;
        *(float4*)&Bs[brow][bcol] = b;
        __syncthreads();
        #pragma unroll
        for (int kk = 0; kk < 16; kk++) {
            float ar[4], br[4];
            *(float4*)ar = *(const float4*)&As[kk][ty*4];
            *(float4*)br = *(const float4*)&Bs[kk][tx*4];
            #pragma unroll
            for (int r = 0; r < 4; r++)
                #pragma unroll
                for (int c = 0; c < 4; c++)
                    acc[r][c] = fmaf(ar[r], br[c], acc[r][c]);
        }
        __syncthreads();
    }
    #pragma unroll
    for (int r = 0; r < 4; r++) {
        int i = bi + ty*4 + r;
        float4 u;
        float* pu = &u.x;
        #pragma unroll
        for (int c = 0; c < 4; c++) {
            float x = acc[r][c];
            pu[c] = x > 0.f ? x : expm1f(x);   // elu, alpha=1
        }
        *(float4*)&g_U[(size_t)i*Fd + bc + tx*4] = u;
        *(float4*)&outU[(size_t)i*Fd + bc + tx*4] = u;
    }
}

// ---------------- GEMM E: sim = U U^T, fused conn epilogue ----------------
// BM=BN=128, BK=8, 256 threads, 8x8 per thread. Grid (16,16).
__global__ void simconn_kernel(const float* __restrict__ dist, const float* __restrict__ deg) {
    __shared__ float As[8][128];
    __shared__ float Bs[8][128];
    int tid = threadIdx.x;
    int bi = blockIdx.y * 128;
    int bj = blockIdx.x * 128;
    int lr = tid >> 1, lc = (tid & 1) << 2;
    int ty = tid >> 4, tx = tid & 15;
    float acc[8][8] = {};
    for (int k0 = 0; k0 < Fd; k0 += 8) {
        float4 a = *(const float4*)&g_U[(size_t)(bi + lr)*Fd + k0 + lc];
        float4 b = *(const float4*)&g_U[(size_t)(bj + lr)*Fd + k0 + lc];
        As[lc+0][lr]=a.x; As[lc+1][lr]=a.y; As[lc+2][lr]=a.z; As[lc+3][lr]=a.w;
        Bs[lc+0][lr]=b.x; Bs[lc+1][lr]=b.y; Bs[lc+2][lr]=b.z; Bs[lc+3][lr]=b.w;
        __syncthreads();
        #pragma unroll
        for (int kk = 0; kk < 8; kk++) {
            float ar[8], br[8];
            *(float4*)&ar[0] = *(const float4*)&As[kk][ty*8];
            *(float4*)&ar[4] = *(const float4*)&As[kk][ty*8+4];
            *(float4*)&br[0] = *(const float4*)&Bs[kk][tx*8];
            *(float4*)&br[4] = *(const float4*)&Bs[kk][tx*8+4];
            #pragma unroll
            for (int r = 0; r < 8; r++)
                #pragma unroll
                for (int c = 0; c < 8; c++)
                    acc[r][c] = fmaf(ar[r], br[c], acc[r][c]);
        }
        __syncthreads();
    }
    #pragma unroll
    for (int r = 0; r < 8; r++) {
        size_t irow = (size_t)(bi + ty*8 + r)*Nn;
        #pragma unroll
        for (int c = 0; c < 8; c++) {
            size_t idx = irow + bj + tx*8 + c;
            float sg = 1.f / (1.f + __expf(-acc[r][c]));
            g_C[idx] = sg * (-dist[idx]) * deg[idx];
        }
    }
}

// ---------------- row layernorm over conn (population var, eps=1e-5) ----------------
__global__ void rownorm_kernel() {
    int i = blockIdx.x;
    int t = threadIdx.x;
    float* row = &g_C[(size_t)i*Nn];
    float s = 0.f, s2 = 0.f;
    for (int j = t; j < Nn; j += 256) {
        float v = row[j];
        s += v; s2 = fmaf(v, v, s2);
    }
    __shared__ float sa[8], sb[8];
    __shared__ float s_mean, s_rstd;
    int w = t >> 5, lane = t & 31;
    #pragma unroll
    for (int o = 16; o > 0; o >>= 1) {
        s  += __shfl_down_sync(0xffffffffu, s, o);
        s2 += __shfl_down_sync(0xffffffffu, s2, o);
    }
    if (lane == 0) { sa[w] = s; sb[w] = s2; }
    __syncthreads();
    if (t == 0) {
        float ts = 0.f, ts2 = 0.f;
        #pragma unroll
        for (int x = 0; x < 8; x++) { ts += sa[x]; ts2 += sb[x]; }
        float mean = ts * (1.f/Nn);
        float var  = ts2 * (1.f/Nn) - mean*mean;
        s_mean = mean;
        s_rstd = rsqrtf(var + 1e-5f);
    }
    __syncthreads();
    float mean = s_mean, rstd = s_rstd;
    for (int j = t; j < Nn; j += 256)
        row[j] = (row[j] - mean) * rstd;
}

// ---------------- out_conn = Cn + Cn^T ----------------
__global__ void symadd_kernel(float* __restrict__ outC) {
    __shared__ float tsh[32][33];
    int bx = blockIdx.x, by = blockIdx.y;
    int tx = threadIdx.x, ty = threadIdx.y;
    #pragma unroll
    for (int r = 0; r < 32; r += 8)
        tsh[ty + r][tx] = g_C[(size_t)(bx*32 + ty + r)*Nn + by*32 + tx];
    __syncthreads();
    #pragma unroll
    for (int r = 0; r < 32; r += 8) {
        size_t i = (size_t)(by*32 + ty + r);
        int j = bx*32 + tx;
        outC[i*Nn + j] = g_C[i*Nn + j] + tsh[tx][ty + r];
    }
}

extern "C" void kernel_launch(void* const* d_in, const int* in_sizes, int n_in,
                              void* d_out, int out_size) {
    const float* X    = (const float*)d_in[0];   // node_features [N,F]
    const float* dist = (const float*)d_in[1];   // edges_features_distance [N,N]
    const float* bond = (const float*)d_in[2];   // edges_features_bond [N,N]
    // d_in[3] = edge_direction (unused by the math)
    const float* deg  = (const float*)d_in[4];   // degree_matrix [N,N]
    const float* Wq   = (const float*)d_in[5];
    const float* Wk   = (const float*)d_in[6];
    const float* Wv   = (const float*)d_in[7];
    const float* wb   = (const float*)d_in[8];
    const float* wbc  = (const float*)d_in[9];
    const float* wg   = (const float*)d_in[10];
    float* out  = (float*)d_out;
    float* outU = out;              // updated_nodes [N,F]
    float* outC = out + Nn*Fd;      // conn [N,N]

    qkv_kernel<<<Nn, 256>>>(X, Wq, Wk, Wv);
    colz_kernel<<<dim3(Nn/256, IC), 256>>>(bond, dist, deg, wb, wbc, wg);
    zred_kernel<<<NH/256, 256>>>();
    attnp_kernel<<<dim3(Nn/256, IC), 256>>>(bond, dist, deg, wb, wbc, wg);
    gemm_pv_kernel<<<dim3(Fd/64, Nn/64), 256>>>(outU);
    simconn_kernel<<<dim3(Nn/128, Nn/128), 256>>>(dist, deg);
    rownorm_kernel<<<Nn, 256>>>();
    symadd_kernel<<<dim3(Nn/32, Nn/32), dim3(32,8)>>>(outC);
}